// round 9
// baseline (speedup 1.0000x reference)
#include <cuda_runtime.h>
#include <cstdint>
#include <math.h>

// LinearFullyConnectedGPLayer on sm_100 (legacy mma.sync tf32 path).
// R9 vs R8: KC 32->16 (stage smem halved) + chunked epilogues, lifting
// occupancy from 3 CTAs/SM to 5 (k1) / 7 (k2) so LDS and tensor-pipe work
// overlap across warps instead of serializing.

namespace {
constexpr int C    = 512;
constexpr int NB   = 8;
constexpr int MAXB = 16384;
constexpr int ROWS = MAXB * NB;

constexpr int TM   = 128;          // rows per CTA (16 batches x 8 blades)
constexpr int TN   = 64;           // channels per CTA
constexpr int KC   = 16;           // K per stage
constexpr int NIT  = C / KC;       // 32
constexpr int NTILE = C / TN;      // 8

constexpr int PIT  = 20;           // stage pitch (floats): 20r+k mod 32 distinct
constexpr int ST_A  = 0;
constexpr int ST_WL = 128 * PIT;               // 2560
constexpr int ST_WR = ST_WL + 64 * PIT;        // 3840
constexpr int ST_SZ = ST_WR + 64 * PIT;        // 5120 floats (k1 stage)
constexpr int K1_SMEM = 2 * ST_SZ * 4;         // 40960 B -> 5 CTAs/SM
constexpr int K2_ST_SZ = (128 + 64) * PIT;     // 3840 floats
constexpr int K2_SMEM  = 2 * K2_ST_SZ * 4;     // 30720 B -> 7 CTAs/SM
constexpr int EPI_P = 36;                      // chunked epilogue pitch
}

// ---- scratch (device globals; no allocation allowed) ----
__device__ float g_a [(size_t)ROWS * C];
__device__ float g_gp[(size_t)ROWS * C];
__device__ float g_wl[(size_t)C * C];
__device__ float g_wr[(size_t)C * C];
__device__ float g_wo[(size_t)C * C];
__device__ float g_normp[(size_t)MAXB * NTILE];
__device__ float g_scale[MAXB];

// ---- helpers ----
__device__ __forceinline__ uint32_t smem_u32(const void* p) {
    uint32_t a;
    asm("{ .reg .u64 t; cvta.to.shared.u64 t, %1; cvt.u32.u64 %0, t; }"
        : "=r"(a) : "l"(p));
    return a;
}
__device__ __forceinline__ float tfround(float x) {
    uint32_t r;
    asm("cvt.rna.tf32.f32 %0, %1;" : "=r"(r) : "f"(x));
    return __uint_as_float(r);
}
__device__ __forceinline__ void cp16(uint32_t dst, const void* src) {
    asm volatile("cp.async.cg.shared.global [%0], [%1], 16;"
                 :: "r"(dst), "l"(src) : "memory");
}
__device__ __forceinline__ void cp_commit() {
    asm volatile("cp.async.commit_group;" ::: "memory");
}
__device__ __forceinline__ void cp_wait1() {
    asm volatile("cp.async.wait_group 1;" ::: "memory");
}
__device__ __forceinline__ void cp_wait0() {
    asm volatile("cp.async.wait_group 0;" ::: "memory");
}
__device__ __forceinline__ void mma8(float (&c)[4], const uint32_t (&a)[4],
                                     uint32_t b0, uint32_t b1) {
    asm volatile(
        "mma.sync.aligned.m16n8k8.row.col.f32.tf32.tf32.f32 "
        "{%0,%1,%2,%3}, {%4,%5,%6,%7}, {%8,%9}, {%0,%1,%2,%3};"
        : "+f"(c[0]), "+f"(c[1]), "+f"(c[2]), "+f"(c[3])
        : "r"(a[0]), "r"(a[1]), "r"(a[2]), "r"(a[3]), "r"(b0), "r"(b1));
}

// ============================================================================
// k_wround: tf32-RNA round weights into g_wl/g_wr/g_wo
// ============================================================================
__global__ void __launch_bounds__(256) k_wround(
    const float* __restrict__ WL, const float* __restrict__ WR,
    const float* __restrict__ WO)
{
    const int q = blockIdx.x * 256 + threadIdx.x;   // float4 index, 196608
    const int e = q * 4;
    const float* src;
    float* dst;
    if (e < 262144)       { src = WL + e;          dst = g_wl + e; }
    else if (e < 524288)  { src = WR + e - 262144; dst = g_wr + e - 262144; }
    else                  { src = WO + e - 524288; dst = g_wo + e - 524288; }
    float4 v = *reinterpret_cast<const float4*>(src);
    v.x = tfround(v.x); v.y = tfround(v.y); v.z = tfround(v.z); v.w = tfround(v.w);
    *reinterpret_cast<float4*>(dst) = v;
}

// ============================================================================
// k_tr: g_a[(b*8+i)*512 + m] = tf32(vec1[(b*512+m)*8 + i]); one batch per CTA
// ============================================================================
__global__ void __launch_bounds__(256) k_tr(const float* __restrict__ vec1) {
    __shared__ float smT[8][516];
    const int b = blockIdx.x;
    const int t = threadIdx.x;
    const float* src = vec1 + (size_t)b * C * NB;
#pragma unroll
    for (int u = 0; u < 4; ++u) {
        int q = t + 256 * u;             // float4 index 0..1023
        int m = q >> 1, ih = q & 1;
        float4 v = *reinterpret_cast<const float4*>(src + (size_t)m * 8 + ih * 4);
        smT[ih * 4 + 0][m] = v.x;
        smT[ih * 4 + 1][m] = v.y;
        smT[ih * 4 + 2][m] = v.z;
        smT[ih * 4 + 3][m] = v.w;
    }
    __syncthreads();
    float* dst = g_a + (size_t)b * NB * C;
#pragma unroll
    for (int u = 0; u < 4; ++u) {
        int q = t + 256 * u;
        int i = q >> 7, mf = q & 127;
        float4 v = *reinterpret_cast<const float4*>(&smT[i][mf * 4]);
        v.x = tfround(v.x); v.y = tfround(v.y); v.z = tfround(v.z); v.w = tfround(v.w);
        *reinterpret_cast<float4*>(dst + (size_t)i * C + mf * 4) = v;
    }
}

// ============================================================================
// k1: L/R GEMMs (shared A) + bias + geometric product -> g_gp
// grid (NTILE, B/16): x = n-tile (fast). 256 thr, 4x2 warps, warp tile 32x32.
// ============================================================================
__global__ void __launch_bounds__(256) k1(
    const float* __restrict__ bLp, const float* __restrict__ bRp)
{
    extern __shared__ float s[];
    const uint32_t sb = smem_u32(s);
    const int t = threadIdx.x;
    const int warp = t >> 5, lane = t & 31;
    const int wm = warp >> 1, wn = warp & 1;
    const int b0r = blockIdx.y * TM;
    const int n0  = blockIdx.x * TN;

    float accL[2][4][4] = {}, accR[2][4][4] = {};

    auto load_stage = [&](int st) {
        const uint32_t base = sb + (uint32_t)((st & 1) * ST_SZ * 4);
        const int k0 = st * KC;
#pragma unroll
        for (int u = 0; u < 2; ++u) {                   // A: 512 chunks
            int idx = t + 256 * u;
            int row = idx >> 2, c4 = idx & 3;
            cp16(base + (uint32_t)((ST_A + row * PIT + c4 * 4) * 4),
                 g_a + (size_t)(b0r + row) * C + k0 + c4 * 4);
        }
        {                                               // WL/WR: 256 each
            int row = t >> 2, c4 = t & 3;
            cp16(base + (uint32_t)((ST_WL + row * PIT + c4 * 4) * 4),
                 g_wl + (size_t)(n0 + row) * C + k0 + c4 * 4);
            cp16(base + (uint32_t)((ST_WR + row * PIT + c4 * 4) * 4),
                 g_wr + (size_t)(n0 + row) * C + k0 + c4 * 4);
        }
        cp_commit();
    };

    auto compute = [&](int buf) {
        const float* base = s + buf * ST_SZ;
        const float* Ab = base + ST_A  + (wm * 32 + (lane >> 2)) * PIT + (lane & 3);
        const float* Lb = base + ST_WL + (wn * 32 + (lane >> 2)) * PIT + (lane & 3);
        const float* Rb = base + ST_WR + (wn * 32 + (lane >> 2)) * PIT + (lane & 3);
#pragma unroll
        for (int kk = 0; kk < KC; kk += 8) {
            uint32_t a[2][4];
#pragma unroll
            for (int rf = 0; rf < 2; ++rf) {
                const float* ap = Ab + rf * 16 * PIT + kk;
                a[rf][0] = __float_as_uint(ap[0]);
                a[rf][1] = __float_as_uint(ap[8 * PIT]);
                a[rf][2] = __float_as_uint(ap[4]);
                a[rf][3] = __float_as_uint(ap[8 * PIT + 4]);
            }
#pragma unroll
            for (int cf = 0; cf < 4; ++cf) {
                const float* lp = Lb + cf * 8 * PIT + kk;
                const float* rp = Rb + cf * 8 * PIT + kk;
                uint32_t l0 = __float_as_uint(lp[0]), l1 = __float_as_uint(lp[4]);
                uint32_t r0 = __float_as_uint(rp[0]), r1 = __float_as_uint(rp[4]);
                mma8(accL[0][cf], a[0], l0, l1);
                mma8(accL[1][cf], a[1], l0, l1);
                mma8(accR[0][cf], a[0], r0, r1);
                mma8(accR[1][cf], a[1], r0, r1);
            }
        }
    };

    load_stage(0);
    load_stage(1);
#pragma unroll 1
    for (int it = 0; it < NIT; ++it) {
        const int buf = it & 1;
        if (it >= NIT - 2) cp_wait0(); else cp_wait1();
        __syncthreads();
        compute(buf);
        __syncthreads();
        if (it + 2 < NIT) load_stage(it + 2);
    }

    // Chunked epilogue: 32 output cols per pass (fits pipe-sized smem).
    float* Ls = s;                    // [128][EPI_P]
    float* Rs = s + 128 * EPI_P;      // [128][EPI_P]
#pragma unroll 1
    for (int cch = 0; cch < 2; ++cch) {
        if (wn == cch) {
#pragma unroll
            for (int rf = 0; rf < 2; ++rf)
#pragma unroll
                for (int cf = 0; cf < 4; ++cf) {
                    const int r = wm * 32 + rf * 16 + (lane >> 2);
                    const int c = cf * 8 + 2 * (lane & 3);   // local 0..31
                    Ls[r * EPI_P + c]           = accL[rf][cf][0];
                    Ls[r * EPI_P + c + 1]       = accL[rf][cf][1];
                    Ls[(r + 8) * EPI_P + c]     = accL[rf][cf][2];
                    Ls[(r + 8) * EPI_P + c + 1] = accL[rf][cf][3];
                    Rs[r * EPI_P + c]           = accR[rf][cf][0];
                    Rs[r * EPI_P + c + 1]       = accR[rf][cf][1];
                    Rs[(r + 8) * EPI_P + c]     = accR[rf][cf][2];
                    Rs[(r + 8) * EPI_P + c + 1] = accR[rf][cf][3];
                }
        }
        __syncthreads();
#pragma unroll
        for (int j = 0; j < 2; ++j) {        // 512 (b,c) pairs in this chunk
            const int p = t + 256 * j;
            const int b = p >> 5, c = p & 31;
            const int nc = n0 + cch * 32 + c;
            float L[8], R[8];
#pragma unroll
            for (int i = 0; i < 8; ++i) {
                L[i] = Ls[(b * 8 + i) * EPI_P + c];
                R[i] = Rs[(b * 8 + i) * EPI_P + c];
            }
            L[0] += bLp[nc];
            R[0] += bRp[nc];
            float g[8];
            g[0] = L[0]*R[0] + L[1]*R[1] + L[2]*R[2] + L[3]*R[3] - L[4]*R[4] - L[5]*R[5] - L[6]*R[6] - L[7]*R[7];
            g[1] = L[1]*R[0] + L[0]*R[1] - L[2]*R[4] - L[3]*R[5] + L[4]*R[2] + L[5]*R[3] - L[6]*R[7] - L[7]*R[6];
            g[2] = L[0]*R[2] + L[2]*R[0] + L[1]*R[4] - L[4]*R[1] - L[3]*R[6] + L[6]*R[3] + L[5]*R[7] + L[7]*R[5];
            g[3] = L[0]*R[3] + L[3]*R[0] + L[1]*R[5] - L[5]*R[1] + L[2]*R[6] - L[6]*R[2] - L[4]*R[7] - L[7]*R[4];
            g[4] = L[0]*R[4] + L[4]*R[0] + L[1]*R[2] - L[2]*R[1] + L[3]*R[7] + L[7]*R[3] - L[5]*R[6] + L[6]*R[5];
            g[5] = L[0]*R[5] + L[5]*R[0] + L[1]*R[3] - L[3]*R[1] - L[2]*R[7] - L[7]*R[2] + L[4]*R[6] - L[6]*R[4];
            g[6] = L[0]*R[6] + L[6]*R[0] + L[2]*R[3] - L[3]*R[2] + L[1]*R[7] + L[7]*R[1] - L[4]*R[5] + L[5]*R[4];
            g[7] = L[0]*R[7] + L[7]*R[0] + L[1]*R[6] + L[6]*R[1] - L[2]*R[5] - L[5]*R[2] + L[3]*R[4] + L[4]*R[3];
#pragma unroll
            for (int i = 0; i < 8; ++i)
                g_gp[(size_t)(b0r + b * 8 + i) * C + nc] = tfround(g[i]);
        }
        __syncthreads();
    }
}

// ============================================================================
// k2: O = gp @ WO^T + bias; store out (b,n,i); norm partials
// grid (NTILE, B/16): x = n-tile (fast).
// ============================================================================
__global__ void __launch_bounds__(256) k2(
    const float* __restrict__ bOp, float* __restrict__ outp)
{
    extern __shared__ float s[];
    const uint32_t sb = smem_u32(s);
    const int t = threadIdx.x;
    const int warp = t >> 5, lane = t & 31;
    const int wm = warp >> 1, wn = warp & 1;
    const int b0r = blockIdx.y * TM;
    const int b0b = blockIdx.y * 16;
    const int n0  = blockIdx.x * TN;

    float acc[2][4][4] = {};

    auto load_stage = [&](int st) {
        const uint32_t base = sb + (uint32_t)((st & 1) * K2_ST_SZ * 4);
        const int k0 = st * KC;
#pragma unroll
        for (int u = 0; u < 2; ++u) {
            int idx = t + 256 * u;
            int row = idx >> 2, c4 = idx & 3;
            cp16(base + (uint32_t)((ST_A + row * PIT + c4 * 4) * 4),
                 g_gp + (size_t)(b0r + row) * C + k0 + c4 * 4);
        }
        {
            int row = t >> 2, c4 = t & 3;
            cp16(base + (uint32_t)((ST_WL + row * PIT + c4 * 4) * 4),
                 g_wo + (size_t)(n0 + row) * C + k0 + c4 * 4);
        }
        cp_commit();
    };

    auto compute = [&](int buf) {
        const float* base = s + buf * K2_ST_SZ;
        const float* Ab = base + ST_A  + (wm * 32 + (lane >> 2)) * PIT + (lane & 3);
        const float* Wb = base + ST_WL + (wn * 32 + (lane >> 2)) * PIT + (lane & 3);
#pragma unroll
        for (int kk = 0; kk < KC; kk += 8) {
            uint32_t a[2][4];
#pragma unroll
            for (int rf = 0; rf < 2; ++rf) {
                const float* ap = Ab + rf * 16 * PIT + kk;
                a[rf][0] = __float_as_uint(ap[0]);
                a[rf][1] = __float_as_uint(ap[8 * PIT]);
                a[rf][2] = __float_as_uint(ap[4]);
                a[rf][3] = __float_as_uint(ap[8 * PIT + 4]);
            }
#pragma unroll
            for (int cf = 0; cf < 4; ++cf) {
                const float* wp = Wb + cf * 8 * PIT + kk;
                uint32_t w0 = __float_as_uint(wp[0]), w1 = __float_as_uint(wp[4]);
                mma8(acc[0][cf], a[0], w0, w1);
                mma8(acc[1][cf], a[1], w0, w1);
            }
        }
    };

    load_stage(0);
    load_stage(1);
#pragma unroll 1
    for (int it = 0; it < NIT; ++it) {
        const int buf = it & 1;
        if (it >= NIT - 2) cp_wait0(); else cp_wait1();
        __syncthreads();
        compute(buf);
        __syncthreads();
        if (it + 2 < NIT) load_stage(it + 2);
    }

    // Chunked epilogue: 32 cols per pass.
    float* Os = s;                    // [128][EPI_P]
    float* Ns = s + 128 * EPI_P;      // [16][64]
#pragma unroll 1
    for (int cch = 0; cch < 2; ++cch) {
        if (wn == cch) {
#pragma unroll
            for (int rf = 0; rf < 2; ++rf)
#pragma unroll
                for (int cf = 0; cf < 4; ++cf) {
                    const int r = wm * 32 + rf * 16 + (lane >> 2);
                    const int c = cf * 8 + 2 * (lane & 3);
                    Os[r * EPI_P + c]           = acc[rf][cf][0];
                    Os[r * EPI_P + c + 1]       = acc[rf][cf][1];
                    Os[(r + 8) * EPI_P + c]     = acc[rf][cf][2];
                    Os[(r + 8) * EPI_P + c + 1] = acc[rf][cf][3];
                }
        }
        __syncthreads();
#pragma unroll
        for (int j = 0; j < 2; ++j) {
            const int p = t + 256 * j;
            const int b = p >> 5, c = p & 31;
            const int nc = n0 + cch * 32 + c;
            float o[8];
#pragma unroll
            for (int i = 0; i < 8; ++i) o[i] = Os[(b * 8 + i) * EPI_P + c];
            o[0] += bOp[nc];
            float ss = 0.f;
#pragma unroll
            for (int i = 0; i < 8; ++i) ss += o[i] * o[i];
            Ns[b * 64 + cch * 32 + c] = sqrtf(ss);
            float* dst = outp + ((size_t)(b0b + b) * C + nc) * NB;
            *reinterpret_cast<float4*>(dst)     = make_float4(o[0], o[1], o[2], o[3]);
            *reinterpret_cast<float4*>(dst + 4) = make_float4(o[4], o[5], o[6], o[7]);
        }
        __syncthreads();
    }

    // norm reduce: warp w -> batches 2w, 2w+1
#pragma unroll
    for (int bb = 0; bb < 2; ++bb) {
        const int b = warp * 2 + bb;
        float v = Ns[b * 64 + lane] + Ns[b * 64 + lane + 32];
#pragma unroll
        for (int off = 16; off > 0; off >>= 1)
            v += __shfl_down_sync(0xffffffffu, v, off);
        if (lane == 0)
            g_normp[(size_t)(b0b + b) * NTILE + blockIdx.x] = v;
    }
}

// ============================================================================
__global__ void __launch_bounds__(256) k_red(int B) {
    const int b = blockIdx.x * 256 + threadIdx.x;
    if (b < B) {
        float v = 0.f;
#pragma unroll
        for (int j = 0; j < NTILE; ++j) v += g_normp[(size_t)b * NTILE + j];
        g_scale[b] = 1.f / (v * (1.f / (float)C) + 1e-6f);
    }
}

__global__ void __launch_bounds__(256) k_scale(float* __restrict__ outp,
                                               const float* __restrict__ an) {
    const size_t idx = (size_t)blockIdx.x * 256 + threadIdx.x;  // float4 index
    const int b = (int)(idx >> 10);
    const int c = ((int)idx >> 1) & (C - 1);
    const float v = an[c] * g_scale[b];
    float4* o4 = reinterpret_cast<float4*>(outp) + idx;
    float4 w = *o4;
    w.x *= v; w.y *= v; w.z *= v; w.w *= v;
    *o4 = w;
}

// ============================================================================
extern "C" void kernel_launch(void* const* d_in, const int* in_sizes, int n_in,
                              void* d_out, int out_size) {
    const float* vec1 = (const float*)d_in[0];
    const float* WL   = (const float*)d_in[1];
    const float* bL   = (const float*)d_in[2];
    const float* WR   = (const float*)d_in[3];
    const float* bR   = (const float*)d_in[4];
    const float* WO   = (const float*)d_in[5];
    const float* bO   = (const float*)d_in[6];
    const float* an   = (const float*)d_in[7];
    float* out = (float*)d_out;

    int B = in_sizes[0] / (C * NB);   // 16384
    if (B > MAXB) B = MAXB;

    cudaFuncSetAttribute(k1, cudaFuncAttributeMaxDynamicSharedMemorySize, K1_SMEM);
    cudaFuncSetAttribute(k2, cudaFuncAttributeMaxDynamicSharedMemorySize, K2_SMEM);

    k_wround<<<768, 256>>>(WL, WR, WO);
    k_tr<<<B, 256>>>(vec1);
    dim3 g(NTILE, B / 16);            // x = n-tile (fast) -> A tiles L2-resident
    k1<<<g, 256, K1_SMEM>>>(bL, bR);
    k2<<<g, 256, K2_SMEM>>>(bO, out);
    k_red<<<(B + 255) / 256, 256>>>(B);
    k_scale<<<(unsigned)((size_t)B * 1024 / 256), 256>>>(out, an);
}

// round 10
// speedup vs baseline: 1.2030x; 1.2030x over previous
#include <cuda_runtime.h>
#include <cstdint>
#include <math.h>

// LinearFullyConnectedGPLayer on sm_100 (legacy mma.sync tf32 path).
// R10 vs R8: (1) K-pair-interleaved operand storage so fragment pairs load as
// LDS.64 (halves mainloop LDS instruction count), PIT=40 for 64-bit
// bank-conflict freedom; (2) k2 warp tile 64x32 (CTA 128x128) cutting
// A-fragment crossbar bytes 25%/MMA.
//
// Interleave: within each 8-column group, orig col c is stored at
//   p8(c) = (c & ~7) | ((c & 3) << 1) | ((c >> 2) & 1)
// so stored[kk + 2q] = orig[kk + q], stored[kk + 2q + 1] = orig[kk + q + 4]
// exactly the (b0,b1)/(a0,a2) fragment pair -> one float2 load.

namespace {
constexpr int C    = 512;
constexpr int NB   = 8;
constexpr int MAXB = 16384;
constexpr int ROWS = MAXB * NB;

constexpr int TM   = 128;
constexpr int KC   = 32;           // K per stage
constexpr int NIT  = C / KC;       // 16
constexpr int NT1  = 8;            // k1 n-tiles (TN=64)
constexpr int NT2  = 4;            // k2 n-tiles (TN=128)

constexpr int PIT  = 40;           // (20*row+q) mod 16 distinct -> LDS.64 clean
// k1 stage: A[128][40], WL[64][40], WR[64][40]
constexpr int ST_A  = 0;
constexpr int ST_WL = 128 * PIT;               // 5120
constexpr int ST_WR = ST_WL + 64 * PIT;        // 7680
constexpr int ST_SZ = ST_WR + 64 * PIT;        // 10240 floats
constexpr int K1_SMEM = 2 * ST_SZ * 4;         // 81920 B
// k2 stage: A[128][40], WO[128][40]
constexpr int ST2_W   = 128 * PIT;             // 5120
constexpr int K2_ST_SZ = 256 * PIT;            // 10240 floats
constexpr int K2_SMEM  = 2 * K2_ST_SZ * 4;     // 81920 B
constexpr int EPI_P  = 68;                     // k1 epilogue pitch
constexpr int EPI_P2 = 132;                    // k2 epilogue pitch
}

// ---- scratch (device globals; no allocation allowed) ----
__device__ float g_a [(size_t)ROWS * C];
__device__ float g_gp[(size_t)ROWS * C];
__device__ float g_wl[(size_t)C * C];
__device__ float g_wr[(size_t)C * C];
__device__ float g_wo[(size_t)C * C];
__device__ float g_normp[(size_t)MAXB * NT2];
__device__ float g_scale[MAXB];

// ---- helpers ----
__device__ __forceinline__ int p8(int c) {
    return (c & ~7) | ((c & 3) << 1) | ((c >> 2) & 1);
}
__device__ __forceinline__ uint32_t smem_u32(const void* p) {
    uint32_t a;
    asm("{ .reg .u64 t; cvta.to.shared.u64 t, %1; cvt.u32.u64 %0, t; }"
        : "=r"(a) : "l"(p));
    return a;
}
__device__ __forceinline__ float tfround(float x) {
    uint32_t r;
    asm("cvt.rna.tf32.f32 %0, %1;" : "=r"(r) : "f"(x));
    return __uint_as_float(r);
}
__device__ __forceinline__ void cp16(uint32_t dst, const void* src) {
    asm volatile("cp.async.cg.shared.global [%0], [%1], 16;"
                 :: "r"(dst), "l"(src) : "memory");
}
__device__ __forceinline__ void cp_commit() {
    asm volatile("cp.async.commit_group;" ::: "memory");
}
__device__ __forceinline__ void cp_wait1() {
    asm volatile("cp.async.wait_group 1;" ::: "memory");
}
__device__ __forceinline__ void cp_wait0() {
    asm volatile("cp.async.wait_group 0;" ::: "memory");
}
__device__ __forceinline__ void mma8(float (&c)[4], const uint32_t (&a)[4],
                                     uint32_t b0, uint32_t b1) {
    asm volatile(
        "mma.sync.aligned.m16n8k8.row.col.f32.tf32.tf32.f32 "
        "{%0,%1,%2,%3}, {%4,%5,%6,%7}, {%8,%9}, {%0,%1,%2,%3};"
        : "+f"(c[0]), "+f"(c[1]), "+f"(c[2]), "+f"(c[3])
        : "r"(a[0]), "r"(a[1]), "r"(a[2]), "r"(a[3]), "r"(b0), "r"(b1));
}

// ============================================================================
// k_wround: tf32-RNA round + K-interleave weights into g_wl/g_wr/g_wo
// ============================================================================
__global__ void __launch_bounds__(256) k_wround(
    const float* __restrict__ WL, const float* __restrict__ WR,
    const float* __restrict__ WO)
{
    const int q = blockIdx.x * 256 + threadIdx.x;   // float4 index, 196608
    const int e = q * 4;
    const float* src;
    float* dst;
    int m;
    if (e < 262144)       { src = WL + e;          dst = g_wl; m = e; }
    else if (e < 524288)  { src = WR + e - 262144; dst = g_wr; m = e - 262144; }
    else                  { src = WO + e - 524288; dst = g_wo; m = e - 524288; }
    const int r = m >> 9, c = m & 511;
    float4 v = *reinterpret_cast<const float4*>(src);
    dst[(size_t)r * C + p8(c + 0)] = tfround(v.x);
    dst[(size_t)r * C + p8(c + 1)] = tfround(v.y);
    dst[(size_t)r * C + p8(c + 2)] = tfround(v.z);
    dst[(size_t)r * C + p8(c + 3)] = tfround(v.w);
}

// ============================================================================
// k_tr: g_a[(b*8+i)*512 + p8(m)] = tf32(vec1[(b*512+m)*8 + i])
// ============================================================================
__global__ void __launch_bounds__(256) k_tr(const float* __restrict__ vec1) {
    __shared__ float smT[8][516];
    const int b = blockIdx.x;
    const int t = threadIdx.x;
    const float* src = vec1 + (size_t)b * C * NB;
#pragma unroll
    for (int u = 0; u < 4; ++u) {
        int q = t + 256 * u;             // float4 index 0..1023
        int m = q >> 1, ih = q & 1;
        float4 v = *reinterpret_cast<const float4*>(src + (size_t)m * 8 + ih * 4);
        smT[ih * 4 + 0][m] = v.x;
        smT[ih * 4 + 1][m] = v.y;
        smT[ih * 4 + 2][m] = v.z;
        smT[ih * 4 + 3][m] = v.w;
    }
    __syncthreads();
    float* dst = g_a + (size_t)b * NB * C;
#pragma unroll
    for (int u = 0; u < 4; ++u) {
        int q = t + 256 * u;
        int i = q >> 7, mf = q & 127;
#pragma unroll
        for (int j = 0; j < 4; ++j) {
            int m = mf * 4 + j;
            dst[(size_t)i * C + p8(m)] = tfround(smT[i][m]);
        }
    }
}

// ============================================================================
// k1: L/R GEMMs (shared A) + bias + geometric product -> g_gp (interleaved)
// grid (NT1, B/16), 256 thr, 4x2 warps, warp tile 32x32.
// ============================================================================
__global__ void __launch_bounds__(256) k1(
    const float* __restrict__ bLp, const float* __restrict__ bRp)
{
    extern __shared__ float s[];
    const uint32_t sb = smem_u32(s);
    const int t = threadIdx.x;
    const int warp = t >> 5, lane = t & 31;
    const int wm = warp >> 1, wn = warp & 1;
    const int b0r = blockIdx.y * TM;
    const int n0  = blockIdx.x * 64;

    float accL[2][4][4] = {}, accR[2][4][4] = {};

    auto load_stage = [&](int st) {
        const uint32_t base = sb + (uint32_t)((st & 1) * ST_SZ * 4);
        const int k0 = st * KC;
#pragma unroll
        for (int u = 0; u < 4; ++u) {                   // A: 1024 chunks
            int idx = t + 256 * u;
            int row = idx >> 3, c4 = idx & 7;
            cp16(base + (uint32_t)((ST_A + row * PIT + c4 * 4) * 4),
                 g_a + (size_t)(b0r + row) * C + k0 + c4 * 4);
        }
#pragma unroll
        for (int u = 0; u < 2; ++u) {                   // WL/WR: 512 each
            int idx = t + 256 * u;
            int row = idx >> 3, c4 = idx & 7;
            cp16(base + (uint32_t)((ST_WL + row * PIT + c4 * 4) * 4),
                 g_wl + (size_t)(n0 + row) * C + k0 + c4 * 4);
            cp16(base + (uint32_t)((ST_WR + row * PIT + c4 * 4) * 4),
                 g_wr + (size_t)(n0 + row) * C + k0 + c4 * 4);
        }
        cp_commit();
    };

    auto compute = [&](int buf) {
        const float* base = s + buf * ST_SZ;
        const int q2 = 2 * (lane & 3);
        const float* Ab = base + ST_A  + (wm * 32 + (lane >> 2)) * PIT + q2;
        const float* Lb = base + ST_WL + (wn * 32 + (lane >> 2)) * PIT + q2;
        const float* Rb = base + ST_WR + (wn * 32 + (lane >> 2)) * PIT + q2;
#pragma unroll
        for (int kk = 0; kk < KC; kk += 8) {
            uint32_t a[2][4];
#pragma unroll
            for (int rf = 0; rf < 2; ++rf) {
                float2 v0 = *reinterpret_cast<const float2*>(Ab + (rf * 16    ) * PIT + kk);
                float2 v1 = *reinterpret_cast<const float2*>(Ab + (rf * 16 + 8) * PIT + kk);
                a[rf][0] = __float_as_uint(v0.x);
                a[rf][1] = __float_as_uint(v1.x);
                a[rf][2] = __float_as_uint(v0.y);
                a[rf][3] = __float_as_uint(v1.y);
            }
#pragma unroll
            for (int cf = 0; cf < 4; ++cf) {
                float2 l = *reinterpret_cast<const float2*>(Lb + cf * 8 * PIT + kk);
                float2 r = *reinterpret_cast<const float2*>(Rb + cf * 8 * PIT + kk);
                uint32_t l0 = __float_as_uint(l.x), l1 = __float_as_uint(l.y);
                uint32_t r0 = __float_as_uint(r.x), r1 = __float_as_uint(r.y);
                mma8(accL[0][cf], a[0], l0, l1);
                mma8(accL[1][cf], a[1], l0, l1);
                mma8(accR[0][cf], a[0], r0, r1);
                mma8(accR[1][cf], a[1], r0, r1);
            }
        }
    };

    load_stage(0);
    load_stage(1);
#pragma unroll 1
    for (int it = 0; it < NIT; ++it) {
        const int buf = it & 1;
        if (it >= NIT - 2) cp_wait0(); else cp_wait1();
        __syncthreads();
        compute(buf);
        __syncthreads();
        if (it + 2 < NIT) load_stage(it + 2);
    }

    // epilogue: accumulators -> smem [128][EPI_P] x2 (reuses pipe smem)
    float* Ls = s;
    float* Rs = s + 128 * EPI_P;
#pragma unroll
    for (int rf = 0; rf < 2; ++rf)
#pragma unroll
        for (int cf = 0; cf < 4; ++cf) {
            const int r = wm * 32 + rf * 16 + (lane >> 2);
            const int c = wn * 32 + cf * 8 + 2 * (lane & 3);
            *reinterpret_cast<float2*>(&Ls[r * EPI_P + c]) =
                make_float2(accL[rf][cf][0], accL[rf][cf][1]);
            *reinterpret_cast<float2*>(&Ls[(r + 8) * EPI_P + c]) =
                make_float2(accL[rf][cf][2], accL[rf][cf][3]);
            *reinterpret_cast<float2*>(&Rs[r * EPI_P + c]) =
                make_float2(accR[rf][cf][0], accR[rf][cf][1]);
            *reinterpret_cast<float2*>(&Rs[(r + 8) * EPI_P + c]) =
                make_float2(accR[rf][cf][2], accR[rf][cf][3]);
        }
    __syncthreads();

    // bias + geometric product (Cl(3,0)) + tf32 round -> g_gp (interleaved col)
#pragma unroll
    for (int j = 0; j < 4; ++j) {
        const int p = t + 256 * j;          // 1024 (b,c) pairs
        const int b = p >> 6, c = p & 63;
        float L[8], R[8];
#pragma unroll
        for (int i = 0; i < 8; ++i) {
            L[i] = Ls[(b * 8 + i) * EPI_P + c];
            R[i] = Rs[(b * 8 + i) * EPI_P + c];
        }
        L[0] += bLp[n0 + c];
        R[0] += bRp[n0 + c];
        float g[8];
        g[0] = L[0]*R[0] + L[1]*R[1] + L[2]*R[2] + L[3]*R[3] - L[4]*R[4] - L[5]*R[5] - L[6]*R[6] - L[7]*R[7];
        g[1] = L[1]*R[0] + L[0]*R[1] - L[2]*R[4] - L[3]*R[5] + L[4]*R[2] + L[5]*R[3] - L[6]*R[7] - L[7]*R[6];
        g[2] = L[0]*R[2] + L[2]*R[0] + L[1]*R[4] - L[4]*R[1] - L[3]*R[6] + L[6]*R[3] + L[5]*R[7] + L[7]*R[5];
        g[3] = L[0]*R[3] + L[3]*R[0] + L[1]*R[5] - L[5]*R[1] + L[2]*R[6] - L[6]*R[2] - L[4]*R[7] - L[7]*R[4];
        g[4] = L[0]*R[4] + L[4]*R[0] + L[1]*R[2] - L[2]*R[1] + L[3]*R[7] + L[7]*R[3] - L[5]*R[6] + L[6]*R[5];
        g[5] = L[0]*R[5] + L[5]*R[0] + L[1]*R[3] - L[3]*R[1] - L[2]*R[7] - L[7]*R[2] + L[4]*R[6] - L[6]*R[4];
        g[6] = L[0]*R[6] + L[6]*R[0] + L[2]*R[3] - L[3]*R[2] + L[1]*R[7] + L[7]*R[1] - L[4]*R[5] + L[5]*R[4];
        g[7] = L[0]*R[7] + L[7]*R[0] + L[1]*R[6] + L[6]*R[1] - L[2]*R[5] - L[5]*R[2] + L[3]*R[4] + L[4]*R[3];
        const int pc = n0 + p8(c);
#pragma unroll
        for (int i = 0; i < 8; ++i)
            g_gp[(size_t)(b0r + b * 8 + i) * C + pc] = tfround(g[i]);
    }
}

// ============================================================================
// k2: O = gp @ WO^T + bias; store out (b,n,i); norm partials
// grid (NT2, B/16), 256 thr, warps 2(wm)x4(wn), warp tile 64x32, CTA 128x128.
// ============================================================================
__global__ void __launch_bounds__(256, 2) k2(
    const float* __restrict__ bOp, float* __restrict__ outp)
{
    extern __shared__ float s[];
    const uint32_t sb = smem_u32(s);
    const int t = threadIdx.x;
    const int warp = t >> 5, lane = t & 31;
    const int wm = warp >> 2, wn = warp & 3;
    const int b0r = blockIdx.y * TM;
    const int b0b = blockIdx.y * 16;
    const int n0  = blockIdx.x * 128;

    float acc[4][4][4] = {};

    auto load_stage = [&](int st) {
        const uint32_t base = sb + (uint32_t)((st & 1) * K2_ST_SZ * 4);
        const int k0 = st * KC;
#pragma unroll
        for (int u = 0; u < 4; ++u) {                   // A: 1024 chunks
            int idx = t + 256 * u;
            int row = idx >> 3, c4 = idx & 7;
            cp16(base + (uint32_t)((row * PIT + c4 * 4) * 4),
                 g_gp + (size_t)(b0r + row) * C + k0 + c4 * 4);
        }
#pragma unroll
        for (int u = 0; u < 4; ++u) {                   // W: 1024 chunks
            int idx = t + 256 * u;
            int row = idx >> 3, c4 = idx & 7;
            cp16(base + (uint32_t)((ST2_W + row * PIT + c4 * 4) * 4),
                 g_wo + (size_t)(n0 + row) * C + k0 + c4 * 4);
        }
        cp_commit();
    };

    auto compute = [&](int buf) {
        const float* base = s + buf * K2_ST_SZ;
        const int q2 = 2 * (lane & 3);
        const float* Ab = base + (wm * 64 + (lane >> 2)) * PIT + q2;
        const float* Wb = base + ST2_W + (wn * 32 + (lane >> 2)) * PIT + q2;
#pragma unroll
        for (int kk = 0; kk < KC; kk += 8) {
            uint32_t a[4][4];
#pragma unroll
            for (int rf = 0; rf < 4; ++rf) {
                float2 v0 = *reinterpret_cast<const float2*>(Ab + (rf * 16    ) * PIT + kk);
                float2 v1 = *reinterpret_cast<const float2*>(Ab + (rf * 16 + 8) * PIT + kk);
                a[rf][0] = __float_as_uint(v0.x);
                a[rf][1] = __float_as_uint(v1.x);
                a[rf][2] = __float_as_uint(v0.y);
                a[rf][3] = __float_as_uint(v1.y);
            }
#pragma unroll
            for (int cf = 0; cf < 4; ++cf) {
                float2 w = *reinterpret_cast<const float2*>(Wb + cf * 8 * PIT + kk);
                uint32_t w0 = __float_as_uint(w.x), w1 = __float_as_uint(w.y);
#pragma unroll
                for (int rf = 0; rf < 4; ++rf)
                    mma8(acc[rf][cf], a[rf], w0, w1);
            }
        }
    };

    load_stage(0);
    load_stage(1);
#pragma unroll 1
    for (int it = 0; it < NIT; ++it) {
        const int buf = it & 1;
        if (it >= NIT - 2) cp_wait0(); else cp_wait1();
        __syncthreads();
        compute(buf);
        __syncthreads();
        if (it + 2 < NIT) load_stage(it + 2);
    }

    // epilogue: Os[128][EPI_P2] + Ns[16][128]
    float* Os = s;
    float* Ns = s + 128 * EPI_P2;
#pragma unroll
    for (int rf = 0; rf < 4; ++rf)
#pragma unroll
        for (int cf = 0; cf < 4; ++cf) {
            const int r = wm * 64 + rf * 16 + (lane >> 2);
            const int c = wn * 32 + cf * 8 + 2 * (lane & 3);
            *reinterpret_cast<float2*>(&Os[r * EPI_P2 + c]) =
                make_float2(acc[rf][cf][0], acc[rf][cf][1]);
            *reinterpret_cast<float2*>(&Os[(r + 8) * EPI_P2 + c]) =
                make_float2(acc[rf][cf][2], acc[rf][cf][3]);
        }
    __syncthreads();

#pragma unroll
    for (int j = 0; j < 8; ++j) {            // 2048 (b,c) pairs
        const int p = t + 256 * j;
        const int b = p >> 7, c = p & 127;
        const int nc = n0 + c;
        float o[8];
#pragma unroll
        for (int i = 0; i < 8; ++i) o[i] = Os[(b * 8 + i) * EPI_P2 + c];
        o[0] += bOp[nc];
        float ss = 0.f;
#pragma unroll
        for (int i = 0; i < 8; ++i) ss += o[i] * o[i];
        Ns[b * 128 + c] = sqrtf(ss);
        float* dst = outp + ((size_t)(b0b + b) * C + nc) * NB;
        *reinterpret_cast<float4*>(dst)     = make_float4(o[0], o[1], o[2], o[3]);
        *reinterpret_cast<float4*>(dst + 4) = make_float4(o[4], o[5], o[6], o[7]);
    }
    __syncthreads();

    // norm reduce: warp w -> batches 2w, 2w+1 (sum over 128 cols)
#pragma unroll
    for (int bb = 0; bb < 2; ++bb) {
        const int b = warp * 2 + bb;
        float v = Ns[b * 128 + lane] + Ns[b * 128 + lane + 32] +
                  Ns[b * 128 + lane + 64] + Ns[b * 128 + lane + 96];
#pragma unroll
        for (int off = 16; off > 0; off >>= 1)
            v += __shfl_down_sync(0xffffffffu, v, off);
        if (lane == 0)
            g_normp[(size_t)(b0b + b) * NT2 + blockIdx.x] = v;
    }
}

// ============================================================================
__global__ void __launch_bounds__(256) k_red(int B) {
    const int b = blockIdx.x * 256 + threadIdx.x;
    if (b < B) {
        float v = 0.f;
#pragma unroll
        for (int j = 0; j < NT2; ++j) v += g_normp[(size_t)b * NT2 + j];
        g_scale[b] = 1.f / (v * (1.f / (float)C) + 1e-6f);
    }
}

__global__ void __launch_bounds__(256) k_scale(float* __restrict__ outp,
                                               const float* __restrict__ an) {
    const size_t idx = (size_t)blockIdx.x * 256 + threadIdx.x;  // float4 index
    const int b = (int)(idx >> 10);
    const int c = ((int)idx >> 1) & (C - 1);
    const float v = an[c] * g_scale[b];
    float4* o4 = reinterpret_cast<float4*>(outp) + idx;
    float4 w = *o4;
    w.x *= v; w.y *= v; w.z *= v; w.w *= v;
    *o4 = w;
}

// ============================================================================
extern "C" void kernel_launch(void* const* d_in, const int* in_sizes, int n_in,
                              void* d_out, int out_size) {
    const float* vec1 = (const float*)d_in[0];
    const float* WL   = (const float*)d_in[1];
    const float* bL   = (const float*)d_in[2];
    const float* WR   = (const float*)d_in[3];
    const float* bR   = (const float*)d_in[4];
    const float* WO   = (const float*)d_in[5];
    const float* bO   = (const float*)d_in[6];
    const float* an   = (const float*)d_in[7];
    float* out = (float*)d_out;

    int B = in_sizes[0] / (C * NB);   // 16384
    if (B > MAXB) B = MAXB;

    cudaFuncSetAttribute(k1, cudaFuncAttributeMaxDynamicSharedMemorySize, K1_SMEM);
    cudaFuncSetAttribute(k2, cudaFuncAttributeMaxDynamicSharedMemorySize, K2_SMEM);

    k_wround<<<768, 256>>>(WL, WR, WO);
    k_tr<<<B, 256>>>(vec1);
    dim3 g1(NT1, B / 16);
    dim3 g2(NT2, B / 16);
    k1<<<g1, 256, K1_SMEM>>>(bL, bR);
    k2<<<g2, 256, K2_SMEM>>>(bO, out);
    k_red<<<(B + 255) / 256, 256>>>(B);
    k_scale<<<(unsigned)((size_t)B * 1024 / 256), 256>>>(out, an);
}

// round 11
// speedup vs baseline: 1.2030x; 1.0000x over previous
#include <cuda_runtime.h>
#include <cstdint>
#include <math.h>

// LinearFullyConnectedGPLayer on sm_100 (legacy mma.sync tf32 path).
// R11 vs R10: both GEMM kernels use 64x64 warp tiles (4 warps, 128 thr,
// CTA 128x128) -> 128 B LDS per MMA (-33%) and 2x per-warp MMA ILP.
// k1 is restructured as ONE GEMM against stacked [WL-tile; WR-tile].

namespace {
constexpr int C    = 512;
constexpr int NB   = 8;
constexpr int MAXB = 16384;
constexpr int ROWS = MAXB * NB;

constexpr int TM   = 128;
constexpr int KC   = 32;           // K per stage
constexpr int NIT  = C / KC;       // 16
constexpr int NT1  = 8;            // k1 n-tiles (64 channels each, L+R stacked)
constexpr int NT2  = 4;            // k2 n-tiles (128 channels each)

constexpr int PIT  = 40;           // LDS.64-clean pitch (R10-validated)
constexpr int ST_W = 128 * PIT;                // W block at 5120 floats
constexpr int ST_SZ = 256 * PIT;               // 10240 floats per stage
constexpr int K_SMEM = 2 * ST_SZ * 4;          // 81920 B -> 2 CTAs/SM
constexpr int EPI_P = 132;                     // epilogue pitch
}

// ---- scratch (device globals; no allocation allowed) ----
__device__ float g_a [(size_t)ROWS * C];
__device__ float g_gp[(size_t)ROWS * C];
__device__ float g_wl[(size_t)C * C];
__device__ float g_wr[(size_t)C * C];
__device__ float g_wo[(size_t)C * C];
__device__ float g_normp[(size_t)MAXB * NT2];
__device__ float g_scale[MAXB];

// ---- helpers ----
__device__ __forceinline__ int p8(int c) {   // K-pair interleave within 8-group
    return (c & ~7) | ((c & 3) << 1) | ((c >> 2) & 1);
}
__device__ __forceinline__ uint32_t smem_u32(const void* p) {
    uint32_t a;
    asm("{ .reg .u64 t; cvta.to.shared.u64 t, %1; cvt.u32.u64 %0, t; }"
        : "=r"(a) : "l"(p));
    return a;
}
__device__ __forceinline__ float tfround(float x) {
    uint32_t r;
    asm("cvt.rna.tf32.f32 %0, %1;" : "=r"(r) : "f"(x));
    return __uint_as_float(r);
}
__device__ __forceinline__ void cp16(uint32_t dst, const void* src) {
    asm volatile("cp.async.cg.shared.global [%0], [%1], 16;"
                 :: "r"(dst), "l"(src) : "memory");
}
__device__ __forceinline__ void cp_commit() {
    asm volatile("cp.async.commit_group;" ::: "memory");
}
__device__ __forceinline__ void cp_wait1() {
    asm volatile("cp.async.wait_group 1;" ::: "memory");
}
__device__ __forceinline__ void cp_wait0() {
    asm volatile("cp.async.wait_group 0;" ::: "memory");
}
__device__ __forceinline__ void mma8(float (&c)[4], const uint32_t (&a)[4],
                                     uint32_t b0, uint32_t b1) {
    asm volatile(
        "mma.sync.aligned.m16n8k8.row.col.f32.tf32.tf32.f32 "
        "{%0,%1,%2,%3}, {%4,%5,%6,%7}, {%8,%9}, {%0,%1,%2,%3};"
        : "+f"(c[0]), "+f"(c[1]), "+f"(c[2]), "+f"(c[3])
        : "r"(a[0]), "r"(a[1]), "r"(a[2]), "r"(a[3]), "r"(b0), "r"(b1));
}

// ============================================================================
// k_wround: tf32-RNA round + K-interleave weights into g_wl/g_wr/g_wo
// ============================================================================
__global__ void __launch_bounds__(256) k_wround(
    const float* __restrict__ WL, const float* __restrict__ WR,
    const float* __restrict__ WO)
{
    const int q = blockIdx.x * 256 + threadIdx.x;   // float4 index, 196608
    const int e = q * 4;
    const float* src;
    float* dst;
    int m;
    if (e < 262144)       { src = WL + e;          dst = g_wl; m = e; }
    else if (e < 524288)  { src = WR + e - 262144; dst = g_wr; m = e - 262144; }
    else                  { src = WO + e - 524288; dst = g_wo; m = e - 524288; }
    const int r = m >> 9, c = m & 511;
    float4 v = *reinterpret_cast<const float4*>(src);
    dst[(size_t)r * C + p8(c + 0)] = tfround(v.x);
    dst[(size_t)r * C + p8(c + 1)] = tfround(v.y);
    dst[(size_t)r * C + p8(c + 2)] = tfround(v.z);
    dst[(size_t)r * C + p8(c + 3)] = tfround(v.w);
}

// ============================================================================
// k_tr: g_a[(b*8+i)*512 + p8(m)] = tf32(vec1[(b*512+m)*8 + i])
// ============================================================================
__global__ void __launch_bounds__(256) k_tr(const float* __restrict__ vec1) {
    __shared__ float smT[8][516];
    const int b = blockIdx.x;
    const int t = threadIdx.x;
    const float* src = vec1 + (size_t)b * C * NB;
#pragma unroll
    for (int u = 0; u < 4; ++u) {
        int q = t + 256 * u;             // float4 index 0..1023
        int m = q >> 1, ih = q & 1;
        float4 v = *reinterpret_cast<const float4*>(src + (size_t)m * 8 + ih * 4);
        smT[ih * 4 + 0][m] = v.x;
        smT[ih * 4 + 1][m] = v.y;
        smT[ih * 4 + 2][m] = v.z;
        smT[ih * 4 + 3][m] = v.w;
    }
    __syncthreads();
    float* dst = g_a + (size_t)b * NB * C;
#pragma unroll
    for (int u = 0; u < 4; ++u) {
        int q = t + 256 * u;
        int i = q >> 7, mf = q & 127;
#pragma unroll
        for (int j = 0; j < 4; ++j) {
            int m = mf * 4 + j;
            dst[(size_t)i * C + p8(m)] = tfround(smT[i][m]);
        }
    }
}

// ============================================================================
// k1: O = A @ [WL-tile; WR-tile]^T, epilogue bias + geometric product -> g_gp
// grid (NT1, B/16), 128 thr, 4 warps 2x2, warp tile 64x64.
// Output tile cols 0-63 = left channels n0..n0+63, cols 64-127 = right.
// ============================================================================
__global__ void __launch_bounds__(128, 2) k1(
    const float* __restrict__ bLp, const float* __restrict__ bRp)
{
    extern __shared__ float s[];
    const uint32_t sb = smem_u32(s);
    const int t = threadIdx.x;
    const int warp = t >> 5, lane = t & 31;
    const int wm = warp >> 1, wn = warp & 1;
    const int b0r = blockIdx.y * TM;
    const int n0  = blockIdx.x * 64;

    float acc[4][8][4] = {};

    auto load_stage = [&](int st) {
        const uint32_t base = sb + (uint32_t)((st & 1) * ST_SZ * 4);
        const int k0 = st * KC;
#pragma unroll
        for (int u = 0; u < 8; ++u) {                   // A: 1024 chunks
            int idx = t + 128 * u;
            int row = idx >> 3, c4 = idx & 7;
            cp16(base + (uint32_t)((row * PIT + c4 * 4) * 4),
                 g_a + (size_t)(b0r + row) * C + k0 + c4 * 4);
        }
#pragma unroll
        for (int u = 0; u < 4; ++u) {                   // WL: 512 chunks
            int idx = t + 128 * u;
            int row = idx >> 3, c4 = idx & 7;
            cp16(base + (uint32_t)((ST_W + row * PIT + c4 * 4) * 4),
                 g_wl + (size_t)(n0 + row) * C + k0 + c4 * 4);
        }
#pragma unroll
        for (int u = 0; u < 4; ++u) {                   // WR: 512 chunks
            int idx = t + 128 * u;
            int row = idx >> 3, c4 = idx & 7;
            cp16(base + (uint32_t)((ST_W + (64 + row) * PIT + c4 * 4) * 4),
                 g_wr + (size_t)(n0 + row) * C + k0 + c4 * 4);
        }
        cp_commit();
    };

    auto compute = [&](int buf) {
        const float* base = s + buf * ST_SZ;
        const int q2 = 2 * (lane & 3);
        const float* Ab = base + (wm * 64 + (lane >> 2)) * PIT + q2;
        const float* Wb = base + ST_W + (wn * 64 + (lane >> 2)) * PIT + q2;
#pragma unroll
        for (int kk = 0; kk < KC; kk += 8) {
            uint32_t a[4][4];
#pragma unroll
            for (int rf = 0; rf < 4; ++rf) {
                float2 v0 = *reinterpret_cast<const float2*>(Ab + (rf * 16    ) * PIT + kk);
                float2 v1 = *reinterpret_cast<const float2*>(Ab + (rf * 16 + 8) * PIT + kk);
                a[rf][0] = __float_as_uint(v0.x);
                a[rf][1] = __float_as_uint(v1.x);
                a[rf][2] = __float_as_uint(v0.y);
                a[rf][3] = __float_as_uint(v1.y);
            }
#pragma unroll
            for (int cf = 0; cf < 8; ++cf) {
                float2 w = *reinterpret_cast<const float2*>(Wb + cf * 8 * PIT + kk);
                uint32_t w0 = __float_as_uint(w.x), w1 = __float_as_uint(w.y);
#pragma unroll
                for (int rf = 0; rf < 4; ++rf)
                    mma8(acc[rf][cf], a[rf], w0, w1);
            }
        }
    };

    load_stage(0);
    load_stage(1);
#pragma unroll 1
    for (int it = 0; it < NIT; ++it) {
        const int buf = it & 1;
        if (it >= NIT - 2) cp_wait0(); else cp_wait1();
        __syncthreads();
        compute(buf);
        __syncthreads();
        if (it + 2 < NIT) load_stage(it + 2);
    }

    // epilogue: acc -> Os[128][EPI_P]; cols 0-63 = L, 64-127 = R
    float* Os = s;
#pragma unroll
    for (int rf = 0; rf < 4; ++rf)
#pragma unroll
        for (int cf = 0; cf < 8; ++cf) {
            const int r = wm * 64 + rf * 16 + (lane >> 2);
            const int c = wn * 64 + cf * 8 + 2 * (lane & 3);
            *reinterpret_cast<float2*>(&Os[r * EPI_P + c]) =
                make_float2(acc[rf][cf][0], acc[rf][cf][1]);
            *reinterpret_cast<float2*>(&Os[(r + 8) * EPI_P + c]) =
                make_float2(acc[rf][cf][2], acc[rf][cf][3]);
        }
    __syncthreads();

    // bias + geometric product (Cl(3,0)) + tf32 round -> g_gp (interleaved col)
#pragma unroll
    for (int j = 0; j < 8; ++j) {
        const int p = t + 128 * j;          // 1024 (b,c) pairs
        const int b = p >> 6, c = p & 63;
        float L[8], R[8];
#pragma unroll
        for (int i = 0; i < 8; ++i) {
            L[i] = Os[(b * 8 + i) * EPI_P + c];
            R[i] = Os[(b * 8 + i) * EPI_P + c + 64];
        }
        L[0] += bLp[n0 + c];
        R[0] += bRp[n0 + c];
        float g[8];
        g[0] = L[0]*R[0] + L[1]*R[1] + L[2]*R[2] + L[3]*R[3] - L[4]*R[4] - L[5]*R[5] - L[6]*R[6] - L[7]*R[7];
        g[1] = L[1]*R[0] + L[0]*R[1] - L[2]*R[4] - L[3]*R[5] + L[4]*R[2] + L[5]*R[3] - L[6]*R[7] - L[7]*R[6];
        g[2] = L[0]*R[2] + L[2]*R[0] + L[1]*R[4] - L[4]*R[1] - L[3]*R[6] + L[6]*R[3] + L[5]*R[7] + L[7]*R[5];
        g[3] = L[0]*R[3] + L[3]*R[0] + L[1]*R[5] - L[5]*R[1] + L[2]*R[6] - L[6]*R[2] - L[4]*R[7] - L[7]*R[4];
        g[4] = L[0]*R[4] + L[4]*R[0] + L[1]*R[2] - L[2]*R[1] + L[3]*R[7] + L[7]*R[3] - L[5]*R[6] + L[6]*R[5];
        g[5] = L[0]*R[5] + L[5]*R[0] + L[1]*R[3] - L[3]*R[1] - L[2]*R[7] - L[7]*R[2] + L[4]*R[6] - L[6]*R[4];
        g[6] = L[0]*R[6] + L[6]*R[0] + L[2]*R[3] - L[3]*R[2] + L[1]*R[7] + L[7]*R[1] - L[4]*R[5] + L[5]*R[4];
        g[7] = L[0]*R[7] + L[7]*R[0] + L[1]*R[6] + L[6]*R[1] - L[2]*R[5] - L[5]*R[2] + L[3]*R[4] + L[4]*R[3];
        const int pc = n0 + p8(c);
#pragma unroll
        for (int i = 0; i < 8; ++i)
            g_gp[(size_t)(b0r + b * 8 + i) * C + pc] = tfround(g[i]);
    }
}

// ============================================================================
// k2: O = gp @ WO^T + bias; store out (b,n,i); norm partials
// grid (NT2, B/16), 128 thr, 4 warps 2x2, warp tile 64x64, CTA 128x128.
// ============================================================================
__global__ void __launch_bounds__(128, 2) k2(
    const float* __restrict__ bOp, float* __restrict__ outp)
{
    extern __shared__ float s[];
    const uint32_t sb = smem_u32(s);
    const int t = threadIdx.x;
    const int warp = t >> 5, lane = t & 31;
    const int wm = warp >> 1, wn = warp & 1;
    const int b0r = blockIdx.y * TM;
    const int b0b = blockIdx.y * 16;
    const int n0  = blockIdx.x * 128;

    float acc[4][8][4] = {};

    auto load_stage = [&](int st) {
        const uint32_t base = sb + (uint32_t)((st & 1) * ST_SZ * 4);
        const int k0 = st * KC;
#pragma unroll
        for (int u = 0; u < 8; ++u) {                   // A: 1024 chunks
            int idx = t + 128 * u;
            int row = idx >> 3, c4 = idx & 7;
            cp16(base + (uint32_t)((row * PIT + c4 * 4) * 4),
                 g_gp + (size_t)(b0r + row) * C + k0 + c4 * 4);
        }
#pragma unroll
        for (int u = 0; u < 8; ++u) {                   // W: 1024 chunks
            int idx = t + 128 * u;
            int row = idx >> 3, c4 = idx & 7;
            cp16(base + (uint32_t)((ST_W + row * PIT + c4 * 4) * 4),
                 g_wo + (size_t)(n0 + row) * C + k0 + c4 * 4);
        }
        cp_commit();
    };

    auto compute = [&](int buf) {
        const float* base = s + buf * ST_SZ;
        const int q2 = 2 * (lane & 3);
        const float* Ab = base + (wm * 64 + (lane >> 2)) * PIT + q2;
        const float* Wb = base + ST_W + (wn * 64 + (lane >> 2)) * PIT + q2;
#pragma unroll
        for (int kk = 0; kk < KC; kk += 8) {
            uint32_t a[4][4];
#pragma unroll
            for (int rf = 0; rf < 4; ++rf) {
                float2 v0 = *reinterpret_cast<const float2*>(Ab + (rf * 16    ) * PIT + kk);
                float2 v1 = *reinterpret_cast<const float2*>(Ab + (rf * 16 + 8) * PIT + kk);
                a[rf][0] = __float_as_uint(v0.x);
                a[rf][1] = __float_as_uint(v1.x);
                a[rf][2] = __float_as_uint(v0.y);
                a[rf][3] = __float_as_uint(v1.y);
            }
#pragma unroll
            for (int cf = 0; cf < 8; ++cf) {
                float2 w = *reinterpret_cast<const float2*>(Wb + cf * 8 * PIT + kk);
                uint32_t w0 = __float_as_uint(w.x), w1 = __float_as_uint(w.y);
#pragma unroll
                for (int rf = 0; rf < 4; ++rf)
                    mma8(acc[rf][cf], a[rf], w0, w1);
            }
        }
    };

    load_stage(0);
    load_stage(1);
#pragma unroll 1
    for (int it = 0; it < NIT; ++it) {
        const int buf = it & 1;
        if (it >= NIT - 2) cp_wait0(); else cp_wait1();
        __syncthreads();
        compute(buf);
        __syncthreads();
        if (it + 2 < NIT) load_stage(it + 2);
    }

    // epilogue: Os[128][EPI_P] + Ns[16][128]
    float* Os = s;
    float* Ns = s + 128 * EPI_P;
#pragma unroll
    for (int rf = 0; rf < 4; ++rf)
#pragma unroll
        for (int cf = 0; cf < 8; ++cf) {
            const int r = wm * 64 + rf * 16 + (lane >> 2);
            const int c = wn * 64 + cf * 8 + 2 * (lane & 3);
            *reinterpret_cast<float2*>(&Os[r * EPI_P + c]) =
                make_float2(acc[rf][cf][0], acc[rf][cf][1]);
            *reinterpret_cast<float2*>(&Os[(r + 8) * EPI_P + c]) =
                make_float2(acc[rf][cf][2], acc[rf][cf][3]);
        }
    __syncthreads();

#pragma unroll
    for (int j = 0; j < 16; ++j) {           // 2048 (b,c) pairs
        const int p = t + 128 * j;
        const int b = p >> 7, c = p & 127;
        const int nc = n0 + c;
        float o[8];
#pragma unroll
        for (int i = 0; i < 8; ++i) o[i] = Os[(b * 8 + i) * EPI_P + c];
        o[0] += bOp[nc];
        float ss = 0.f;
#pragma unroll
        for (int i = 0; i < 8; ++i) ss += o[i] * o[i];
        Ns[b * 128 + c] = sqrtf(ss);
        float* dst = outp + ((size_t)(b0b + b) * C + nc) * NB;
        *reinterpret_cast<float4*>(dst)     = make_float4(o[0], o[1], o[2], o[3]);
        *reinterpret_cast<float4*>(dst + 4) = make_float4(o[4], o[5], o[6], o[7]);
    }
    __syncthreads();

    // norm reduce: warp w -> batches 4w..4w+3 (sum over this tile's 128 cols)
#pragma unroll
    for (int bb = 0; bb < 4; ++bb) {
        const int b = warp * 4 + bb;
        float v = Ns[b * 128 + lane] + Ns[b * 128 + lane + 32] +
                  Ns[b * 128 + lane + 64] + Ns[b * 128 + lane + 96];
#pragma unroll
        for (int off = 16; off > 0; off >>= 1)
            v += __shfl_down_sync(0xffffffffu, v, off);
        if (lane == 0)
            g_normp[(size_t)(b0b + b) * NT2 + blockIdx.x] = v;
    }
}

// ============================================================================
__global__ void __launch_bounds__(256) k_red(int B) {
    const int b = blockIdx.x * 256 + threadIdx.x;
    if (b < B) {
        float v = 0.f;
#pragma unroll
        for (int j = 0; j < NT2; ++j) v += g_normp[(size_t)b * NT2 + j];
        g_scale[b] = 1.f / (v * (1.f / (float)C) + 1e-6f);
    }
}

__global__ void __launch_bounds__(256) k_scale(float* __restrict__ outp,
                                               const float* __restrict__ an) {
    const size_t idx = (size_t)blockIdx.x * 256 + threadIdx.x;  // float4 index
    const int b = (int)(idx >> 10);
    const int c = ((int)idx >> 1) & (C - 1);
    const float v = an[c] * g_scale[b];
    float4* o4 = reinterpret_cast<float4*>(outp) + idx;
    float4 w = *o4;
    w.x *= v; w.y *= v; w.z *= v; w.w *= v;
    *o4 = w;
}

// ============================================================================
extern "C" void kernel_launch(void* const* d_in, const int* in_sizes, int n_in,
                              void* d_out, int out_size) {
    const float* vec1 = (const float*)d_in[0];
    const float* WL   = (const float*)d_in[1];
    const float* bL   = (const float*)d_in[2];
    const float* WR   = (const float*)d_in[3];
    const float* bR   = (const float*)d_in[4];
    const float* WO   = (const float*)d_in[5];
    const float* bO   = (const float*)d_in[6];
    const float* an   = (const float*)d_in[7];
    float* out = (float*)d_out;

    int B = in_sizes[0] / (C * NB);   // 16384
    if (B > MAXB) B = MAXB;

    cudaFuncSetAttribute(k1, cudaFuncAttributeMaxDynamicSharedMemorySize, K_SMEM);
    cudaFuncSetAttribute(k2, cudaFuncAttributeMaxDynamicSharedMemorySize, K_SMEM);

    k_wround<<<768, 256>>>(WL, WR, WO);
    k_tr<<<B, 256>>>(vec1);
    dim3 g1(NT1, B / 16);
    dim3 g2(NT2, B / 16);
    k1<<<g1, 128, K_SMEM>>>(bL, bR);
    k2<<<g2, 128, K_SMEM>>>(bO, out);
    k_red<<<(B + 255) / 256, 256>>>(B);
    k_scale<<<(unsigned)((size_t)B * 1024 / 256), 256>>>(out, an);
}

// round 12
// speedup vs baseline: 2.1176x; 1.7602x over previous
#include <cuda_runtime.h>
#include <cuda_fp16.h>
#include <cstdint>
#include <math.h>

// LinearFullyConnectedGPLayer on sm_100 (legacy mma.sync path).
// R12: operands stored as fp16 (same 10-bit mantissa as tf32 -> same error),
// GEMMs use mma.m16n8k16.f32.f16.f16.f32 -> HALF the MMA instructions and
// half the operand bytes everywhere. Config: 256 thr, 8 warps 2x4, warp tile
// 64x32, CTA 128x128 (k1 = single GEMM vs stacked [WL;WR]). KC=64, PIT=80
// halves (perfect LDS.64 bank pattern), K-pair interleave p16 so every
// fragment pair is one LDS.64.

namespace {
constexpr int C    = 512;
constexpr int NB   = 8;
constexpr int MAXB = 16384;
constexpr int ROWS = MAXB * NB;

constexpr int TM   = 128;
constexpr int KC   = 64;            // K halves per stage
constexpr int NIT  = C / KC;        // 8
constexpr int NT1  = 8;             // k1 n-tiles (64 ch, L+R stacked)
constexpr int NT2  = 4;             // k2 n-tiles (128 ch)

constexpr int PIT  = 80;            // halves per smem row; (20r+q)%16 distinct
constexpr int ST_W  = 128 * PIT;    // W block offset (halves)
constexpr int ST_SZ = 256 * PIT;    // 20480 halves per stage
constexpr int PIPE_B = 2 * ST_SZ * 2;        // 81920 B
constexpr int EPI_P  = 132;
constexpr int K_SMEM = PIPE_B;               // >= epilogue needs (75776)
}

// ---- scratch (device globals; no allocation allowed) ----
__device__ __half g_a [(size_t)ROWS * C];
__device__ __half g_gp[(size_t)ROWS * C];
__device__ __half g_wl[(size_t)C * C];
__device__ __half g_wr[(size_t)C * C];
__device__ __half g_wo[(size_t)C * C];
__device__ float  g_normp[(size_t)MAXB * NT2];
__device__ float  g_scale[MAXB];

// ---- helpers ----
// Within each 16-group: pairs (2q,2q+1) and (2q+8,2q+9) stored adjacently:
// pos 4q..4q+3 hold k = 2q, 2q+1, 2q+8, 2q+9.
__device__ __forceinline__ int p16(int k) {
    int g = k & 15, p = g >> 1, o = g & 1;
    int np = ((p & 3) << 1) | (p >> 2);
    return (k & ~15) | (np << 1) | o;
}
__device__ __forceinline__ uint32_t smem_u32(const void* p) {
    uint32_t a;
    asm("{ .reg .u64 t; cvta.to.shared.u64 t, %1; cvt.u32.u64 %0, t; }"
        : "=r"(a) : "l"(p));
    return a;
}
__device__ __forceinline__ void cp16(uint32_t dst, const void* src) {
    asm volatile("cp.async.cg.shared.global [%0], [%1], 16;"
                 :: "r"(dst), "l"(src) : "memory");
}
__device__ __forceinline__ void cp_commit() {
    asm volatile("cp.async.commit_group;" ::: "memory");
}
__device__ __forceinline__ void cp_wait1() {
    asm volatile("cp.async.wait_group 1;" ::: "memory");
}
__device__ __forceinline__ void cp_wait0() {
    asm volatile("cp.async.wait_group 0;" ::: "memory");
}
__device__ __forceinline__ void mma16(float (&c)[4], uint32_t a0, uint32_t a1,
                                      uint32_t a2, uint32_t a3,
                                      uint32_t b0, uint32_t b1) {
    asm volatile(
        "mma.sync.aligned.m16n8k16.row.col.f32.f16.f16.f32 "
        "{%0,%1,%2,%3}, {%4,%5,%6,%7}, {%8,%9}, {%0,%1,%2,%3};"
        : "+f"(c[0]), "+f"(c[1]), "+f"(c[2]), "+f"(c[3])
        : "r"(a0), "r"(a1), "r"(a2), "r"(a3), "r"(b0), "r"(b1));
}

// ============================================================================
// k_wround: fp16-round + K-interleave weights
// ============================================================================
__global__ void __launch_bounds__(256) k_wround(
    const float* __restrict__ WL, const float* __restrict__ WR,
    const float* __restrict__ WO)
{
    const int q = blockIdx.x * 256 + threadIdx.x;   // float4 index, 196608
    const int e = q * 4;
    const float* src;
    __half* dst;
    int m;
    if (e < 262144)       { src = WL + e;          dst = g_wl; m = e; }
    else if (e < 524288)  { src = WR + e - 262144; dst = g_wr; m = e - 262144; }
    else                  { src = WO + e - 524288; dst = g_wo; m = e - 524288; }
    const int r = m >> 9, c = m & 511;
    float4 v = *reinterpret_cast<const float4*>(src);
    dst[(size_t)r * C + p16(c + 0)] = __float2half_rn(v.x);
    dst[(size_t)r * C + p16(c + 1)] = __float2half_rn(v.y);
    dst[(size_t)r * C + p16(c + 2)] = __float2half_rn(v.z);
    dst[(size_t)r * C + p16(c + 3)] = __float2half_rn(v.w);
}

// ============================================================================
// k_tr: g_a[(b*8+i)*512 + p16(m)] = fp16(vec1[(b*512+m)*8 + i])
// ============================================================================
__global__ void __launch_bounds__(256) k_tr(const float* __restrict__ vec1) {
    __shared__ float smT[8][516];
    const int b = blockIdx.x;
    const int t = threadIdx.x;
    const float* src = vec1 + (size_t)b * C * NB;
#pragma unroll
    for (int u = 0; u < 4; ++u) {
        int q = t + 256 * u;             // float4 index 0..1023
        int m = q >> 1, ih = q & 1;
        float4 v = *reinterpret_cast<const float4*>(src + (size_t)m * 8 + ih * 4);
        smT[ih * 4 + 0][m] = v.x;
        smT[ih * 4 + 1][m] = v.y;
        smT[ih * 4 + 2][m] = v.z;
        smT[ih * 4 + 3][m] = v.w;
    }
    __syncthreads();
    __half* dst = g_a + (size_t)b * NB * C;
#pragma unroll
    for (int u = 0; u < 4; ++u) {
        int q = t + 256 * u;
        int i = q >> 7, mf = q & 127;
#pragma unroll
        for (int j = 0; j < 4; ++j) {
            int m = mf * 4 + j;
            dst[(size_t)i * C + p16(m)] = __float2half_rn(smT[i][m]);
        }
    }
}

// ============================================================================
// Shared mainloop body (A rows 0-127, W rows 0-127 of the stage)
// warp tile 64x32: wm = warp>>2 (2), wn = warp&3 (4)
// ============================================================================
struct Frag { float acc[4][4][4]; };

template <const __half* const* dummy>  // (unused; keep single definition style)
struct Never {};

__device__ __forceinline__ void gemm_mainloop(
    const __half* sbase_h, uint32_t sb, const __half* gA, const __half* gW,
    int b0r, int n0_rows, float (&acc)[4][4][4], int t, int wm, int wn, int lane)
{
    auto load_stage = [&](int st) {
        const uint32_t base = sb + (uint32_t)((st & 1) * ST_SZ * 2);
        const int k0 = st * KC;
#pragma unroll
        for (int u = 0; u < 4; ++u) {                   // A: 1024 chunks
            int idx = t + 256 * u;
            int row = idx >> 3, c4 = idx & 7;
            cp16(base + (uint32_t)((row * PIT + c4 * 8) * 2),
                 gA + (size_t)(b0r + row) * C + k0 + c4 * 8);
        }
#pragma unroll
        for (int u = 0; u < 4; ++u) {                   // W: 1024 chunks
            int idx = t + 256 * u;
            int row = idx >> 3, c4 = idx & 7;
            cp16(base + (uint32_t)((ST_W + row * PIT + c4 * 8) * 2),
                 gW + (size_t)(n0_rows + row) * C + k0 + c4 * 8);
        }
        cp_commit();
    };

    auto compute = [&](int buf) {
        const __half* base = sbase_h + buf * ST_SZ;
        const int q4 = 4 * (lane & 3);
        const __half* Ab = base + (wm * 64 + (lane >> 2)) * PIT + q4;
        const __half* Wb = base + ST_W + (wn * 32 + (lane >> 2)) * PIT + q4;
#pragma unroll
        for (int kk = 0; kk < KC; kk += 16) {
            uint2 av[4][2];
#pragma unroll
            for (int rf = 0; rf < 4; ++rf) {
                av[rf][0] = *reinterpret_cast<const uint2*>(Ab + (rf * 16    ) * PIT + kk);
                av[rf][1] = *reinterpret_cast<const uint2*>(Ab + (rf * 16 + 8) * PIT + kk);
            }
#pragma unroll
            for (int cf = 0; cf < 4; ++cf) {
                uint2 w = *reinterpret_cast<const uint2*>(Wb + cf * 8 * PIT + kk);
#pragma unroll
                for (int rf = 0; rf < 4; ++rf)
                    mma16(acc[rf][cf], av[rf][0].x, av[rf][1].x,
                          av[rf][0].y, av[rf][1].y, w.x, w.y);
            }
        }
    };

    load_stage(0);
    load_stage(1);
#pragma unroll 1
    for (int it = 0; it < NIT; ++it) {
        const int buf = it & 1;
        if (it >= NIT - 2) cp_wait0(); else cp_wait1();
        __syncthreads();
        compute(buf);
        __syncthreads();
        if (it + 2 < NIT) load_stage(it + 2);
    }
}

// ============================================================================
// k1: O = A @ [WL-tile; WR-tile]^T -> bias + geometric product -> g_gp (fp16)
// grid (NT1, B/16), 256 thr. Output cols 0-63 = L, 64-127 = R.
// ============================================================================
__global__ void __launch_bounds__(256, 2) k1(
    const float* __restrict__ bLp, const float* __restrict__ bRp)
{
    extern __shared__ char dsm[];
    __half* sh = reinterpret_cast<__half*>(dsm);
    const uint32_t sb = smem_u32(dsm);
    const int t = threadIdx.x;
    const int warp = t >> 5, lane = t & 31;
    const int wm = warp >> 2, wn = warp & 3;
    const int b0r = blockIdx.y * TM;
    const int n0  = blockIdx.x * 64;

    float acc[4][4][4] = {};

    // Stacked W: rows 0-63 from g_wl[n0..], rows 64-127 from g_wr[n0..].
    // gemm_mainloop loads gW rows n0_rows..n0_rows+127 contiguously, so we
    // inline a custom loader here instead.
    {
        auto load_stage = [&](int st) {
            const uint32_t base = sb + (uint32_t)((st & 1) * ST_SZ * 2);
            const int k0 = st * KC;
#pragma unroll
            for (int u = 0; u < 4; ++u) {               // A
                int idx = t + 256 * u;
                int row = idx >> 3, c4 = idx & 7;
                cp16(base + (uint32_t)((row * PIT + c4 * 8) * 2),
                     g_a + (size_t)(b0r + row) * C + k0 + c4 * 8);
            }
#pragma unroll
            for (int u = 0; u < 2; ++u) {               // WL rows 0-63
                int idx = t + 256 * u;
                int row = idx >> 3, c4 = idx & 7;
                cp16(base + (uint32_t)((ST_W + row * PIT + c4 * 8) * 2),
                     g_wl + (size_t)(n0 + row) * C + k0 + c4 * 8);
            }
#pragma unroll
            for (int u = 0; u < 2; ++u) {               // WR rows 64-127
                int idx = t + 256 * u;
                int row = idx >> 3, c4 = idx & 7;
                cp16(base + (uint32_t)((ST_W + (64 + row) * PIT + c4 * 8) * 2),
                     g_wr + (size_t)(n0 + row) * C + k0 + c4 * 8);
            }
            cp_commit();
        };
        auto compute = [&](int buf) {
            const __half* base = sh + buf * ST_SZ;
            const int q4 = 4 * (lane & 3);
            const __half* Ab = base + (wm * 64 + (lane >> 2)) * PIT + q4;
            const __half* Wb = base + ST_W + (wn * 32 + (lane >> 2)) * PIT + q4;
#pragma unroll
            for (int kk = 0; kk < KC; kk += 16) {
                uint2 av[4][2];
#pragma unroll
                for (int rf = 0; rf < 4; ++rf) {
                    av[rf][0] = *reinterpret_cast<const uint2*>(Ab + (rf * 16    ) * PIT + kk);
                    av[rf][1] = *reinterpret_cast<const uint2*>(Ab + (rf * 16 + 8) * PIT + kk);
                }
#pragma unroll
                for (int cf = 0; cf < 4; ++cf) {
                    uint2 w = *reinterpret_cast<const uint2*>(Wb + cf * 8 * PIT + kk);
#pragma unroll
                    for (int rf = 0; rf < 4; ++rf)
                        mma16(acc[rf][cf], av[rf][0].x, av[rf][1].x,
                              av[rf][0].y, av[rf][1].y, w.x, w.y);
                }
            }
        };
        load_stage(0);
        load_stage(1);
#pragma unroll 1
        for (int it = 0; it < NIT; ++it) {
            const int buf = it & 1;
            if (it >= NIT - 2) cp_wait0(); else cp_wait1();
            __syncthreads();
            compute(buf);
            __syncthreads();
            if (it + 2 < NIT) load_stage(it + 2);
        }
    }

    // epilogue: acc -> Os[128][EPI_P] (cols 0-63 = L, 64-127 = R)
    float* Os = reinterpret_cast<float*>(dsm);
#pragma unroll
    for (int rf = 0; rf < 4; ++rf)
#pragma unroll
        for (int cf = 0; cf < 4; ++cf) {
            const int r = wm * 64 + rf * 16 + (lane >> 2);
            const int c = wn * 32 + cf * 8 + 2 * (lane & 3);
            *reinterpret_cast<float2*>(&Os[r * EPI_P + c]) =
                make_float2(acc[rf][cf][0], acc[rf][cf][1]);
            *reinterpret_cast<float2*>(&Os[(r + 8) * EPI_P + c]) =
                make_float2(acc[rf][cf][2], acc[rf][cf][3]);
        }
    __syncthreads();

    // bias + geometric product (Cl(3,0)) -> g_gp as fp16 (p16-interleaved col)
#pragma unroll
    for (int j = 0; j < 4; ++j) {
        const int p = t + 256 * j;          // 1024 (b,c) pairs
        const int b = p >> 6, c = p & 63;
        float L[8], R[8];
#pragma unroll
        for (int i = 0; i < 8; ++i) {
            L[i] = Os[(b * 8 + i) * EPI_P + c];
            R[i] = Os[(b * 8 + i) * EPI_P + c + 64];
        }
        L[0] += bLp[n0 + c];
        R[0] += bRp[n0 + c];
        float g[8];
        g[0] = L[0]*R[0] + L[1]*R[1] + L[2]*R[2] + L[3]*R[3] - L[4]*R[4] - L[5]*R[5] - L[6]*R[6] - L[7]*R[7];
        g[1] = L[1]*R[0] + L[0]*R[1] - L[2]*R[4] - L[3]*R[5] + L[4]*R[2] + L[5]*R[3] - L[6]*R[7] - L[7]*R[6];
        g[2] = L[0]*R[2] + L[2]*R[0] + L[1]*R[4] - L[4]*R[1] - L[3]*R[6] + L[6]*R[3] + L[5]*R[7] + L[7]*R[5];
        g[3] = L[0]*R[3] + L[3]*R[0] + L[1]*R[5] - L[5]*R[1] + L[2]*R[6] - L[6]*R[2] - L[4]*R[7] - L[7]*R[4];
        g[4] = L[0]*R[4] + L[4]*R[0] + L[1]*R[2] - L[2]*R[1] + L[3]*R[7] + L[7]*R[3] - L[5]*R[6] + L[6]*R[5];
        g[5] = L[0]*R[5] + L[5]*R[0] + L[1]*R[3] - L[3]*R[1] - L[2]*R[7] - L[7]*R[2] + L[4]*R[6] - L[6]*R[4];
        g[6] = L[0]*R[6] + L[6]*R[0] + L[2]*R[3] - L[3]*R[2] + L[1]*R[7] + L[7]*R[1] - L[4]*R[5] + L[5]*R[4];
        g[7] = L[0]*R[7] + L[7]*R[0] + L[1]*R[6] + L[6]*R[1] - L[2]*R[5] - L[5]*R[2] + L[3]*R[4] + L[4]*R[3];
        const int pc = n0 + p16(c);
#pragma unroll
        for (int i = 0; i < 8; ++i)
            g_gp[(size_t)(b0r + b * 8 + i) * C + pc] = __float2half_rn(g[i]);
    }
}

// ============================================================================
// k2: O = gp @ WO^T + bias; store out (b,n,i) fp32; norm partials
// grid (NT2, B/16), 256 thr.
// ============================================================================
__global__ void __launch_bounds__(256, 2) k2(
    const float* __restrict__ bOp, float* __restrict__ outp)
{
    extern __shared__ char dsm[];
    __half* sh = reinterpret_cast<__half*>(dsm);
    const uint32_t sb = smem_u32(dsm);
    const int t = threadIdx.x;
    const int warp = t >> 5, lane = t & 31;
    const int wm = warp >> 2, wn = warp & 3;
    const int b0r = blockIdx.y * TM;
    const int b0b = blockIdx.y * 16;
    const int n0  = blockIdx.x * 128;

    float acc[4][4][4] = {};

    {
        auto load_stage = [&](int st) {
            const uint32_t base = sb + (uint32_t)((st & 1) * ST_SZ * 2);
            const int k0 = st * KC;
#pragma unroll
            for (int u = 0; u < 4; ++u) {               // A
                int idx = t + 256 * u;
                int row = idx >> 3, c4 = idx & 7;
                cp16(base + (uint32_t)((row * PIT + c4 * 8) * 2),
                     g_gp + (size_t)(b0r + row) * C + k0 + c4 * 8);
            }
#pragma unroll
            for (int u = 0; u < 4; ++u) {               // W
                int idx = t + 256 * u;
                int row = idx >> 3, c4 = idx & 7;
                cp16(base + (uint32_t)((ST_W + row * PIT + c4 * 8) * 2),
                     g_wo + (size_t)(n0 + row) * C + k0 + c4 * 8);
            }
            cp_commit();
        };
        auto compute = [&](int buf) {
            const __half* base = sh + buf * ST_SZ;
            const int q4 = 4 * (lane & 3);
            const __half* Ab = base + (wm * 64 + (lane >> 2)) * PIT + q4;
            const __half* Wb = base + ST_W + (wn * 32 + (lane >> 2)) * PIT + q4;
#pragma unroll
            for (int kk = 0; kk < KC; kk += 16) {
                uint2 av[4][2];
#pragma unroll
                for (int rf = 0; rf < 4; ++rf) {
                    av[rf][0] = *reinterpret_cast<const uint2*>(Ab + (rf * 16    ) * PIT + kk);
                    av[rf][1] = *reinterpret_cast<const uint2*>(Ab + (rf * 16 + 8) * PIT + kk);
                }
#pragma unroll
                for (int cf = 0; cf < 4; ++cf) {
                    uint2 w = *reinterpret_cast<const uint2*>(Wb + cf * 8 * PIT + kk);
#pragma unroll
                    for (int rf = 0; rf < 4; ++rf)
                        mma16(acc[rf][cf], av[rf][0].x, av[rf][1].x,
                              av[rf][0].y, av[rf][1].y, w.x, w.y);
                }
            }
        };
        load_stage(0);
        load_stage(1);
#pragma unroll 1
        for (int it = 0; it < NIT; ++it) {
            const int buf = it & 1;
            if (it >= NIT - 2) cp_wait0(); else cp_wait1();
            __syncthreads();
            compute(buf);
            __syncthreads();
            if (it + 2 < NIT) load_stage(it + 2);
        }
    }

    // epilogue: Os[128][EPI_P] + Ns[16][128]
    float* Os = reinterpret_cast<float*>(dsm);
    float* Ns = Os + 128 * EPI_P;
#pragma unroll
    for (int rf = 0; rf < 4; ++rf)
#pragma unroll
        for (int cf = 0; cf < 4; ++cf) {
            const int r = wm * 64 + rf * 16 + (lane >> 2);
            const int c = wn * 32 + cf * 8 + 2 * (lane & 3);
            *reinterpret_cast<float2*>(&Os[r * EPI_P + c]) =
                make_float2(acc[rf][cf][0], acc[rf][cf][1]);
            *reinterpret_cast<float2*>(&Os[(r + 8) * EPI_P + c]) =
                make_float2(acc[rf][cf][2], acc[rf][cf][3]);
        }
    __syncthreads();

#pragma unroll
    for (int j = 0; j < 8; ++j) {            // 2048 (b,c) pairs
        const int p = t + 256 * j;
        const int b = p >> 7, c = p & 127;
        const int nc = n0 + c;
        float o[8];
#pragma unroll
        for (int i = 0; i < 8; ++i) o[i] = Os[(b * 8 + i) * EPI_P + c];
        o[0] += bOp[nc];
        float ss = 0.f;
#pragma unroll
        for (int i = 0; i < 8; ++i) ss += o[i] * o[i];
        Ns[b * 128 + c] = sqrtf(ss);
        float* dst = outp + ((size_t)(b0b + b) * C + nc) * NB;
        *reinterpret_cast<float4*>(dst)     = make_float4(o[0], o[1], o[2], o[3]);
        *reinterpret_cast<float4*>(dst + 4) = make_float4(o[4], o[5], o[6], o[7]);
    }
    __syncthreads();

    // norm reduce: warp w -> batches 2w, 2w+1
#pragma unroll
    for (int bb = 0; bb < 2; ++bb) {
        const int b = warp * 2 + bb;
        float v = Ns[b * 128 + lane] + Ns[b * 128 + lane + 32] +
                  Ns[b * 128 + lane + 64] + Ns[b * 128 + lane + 96];
#pragma unroll
        for (int off = 16; off > 0; off >>= 1)
            v += __shfl_down_sync(0xffffffffu, v, off);
        if (lane == 0)
            g_normp[(size_t)(b0b + b) * NT2 + blockIdx.x] = v;
    }
}

// ============================================================================
__global__ void __launch_bounds__(256) k_red(int B) {
    const int b = blockIdx.x * 256 + threadIdx.x;
    if (b < B) {
        float v = 0.f;
#pragma unroll
        for (int j = 0; j < NT2; ++j) v += g_normp[(size_t)b * NT2 + j];
        g_scale[b] = 1.f / (v * (1.f / (float)C) + 1e-6f);
    }
}

__global__ void __launch_bounds__(256) k_scale(float* __restrict__ outp,
                                               const float* __restrict__ an) {
    const size_t idx = (size_t)blockIdx.x * 256 + threadIdx.x;  // float4 index
    const int b = (int)(idx >> 10);
    const int c = ((int)idx >> 1) & (C - 1);
    const float v = an[c] * g_scale[b];
    float4* o4 = reinterpret_cast<float4*>(outp) + idx;
    float4 w = *o4;
    w.x *= v; w.y *= v; w.z *= v; w.w *= v;
    *o4 = w;
}

// ============================================================================
extern "C" void kernel_launch(void* const* d_in, const int* in_sizes, int n_in,
                              void* d_out, int out_size) {
    const float* vec1 = (const float*)d_in[0];
    const float* WL   = (const float*)d_in[1];
    const float* bL   = (const float*)d_in[2];
    const float* WR   = (const float*)d_in[3];
    const float* bR   = (const float*)d_in[4];
    const float* WO   = (const float*)d_in[5];
    const float* bO   = (const float*)d_in[6];
    const float* an   = (const float*)d_in[7];
    float* out = (float*)d_out;

    int B = in_sizes[0] / (C * NB);   // 16384
    if (B > MAXB) B = MAXB;

    cudaFuncSetAttribute(k1, cudaFuncAttributeMaxDynamicSharedMemorySize, K_SMEM);
    cudaFuncSetAttribute(k2, cudaFuncAttributeMaxDynamicSharedMemorySize, K_SMEM);

    k_wround<<<768, 256>>>(WL, WR, WO);
    k_tr<<<B, 256>>>(vec1);
    dim3 g1(NT1, B / 16);
    dim3 g2(NT2, B / 16);
    k1<<<g1, 256, K_SMEM>>>(bL, bR);
    k2<<<g2, 256, K_SMEM>>>(bO, out);
    k_red<<<(B + 255) / 256, 256>>>(B);
    k_scale<<<(unsigned)((size_t)B * 1024 / 256), 256>>>(out, an);
}